// round 7
// baseline (speedup 1.0000x reference)
#include <cuda_runtime.h>

// y[o*48+p, n, m] = sum_i W0[p,i] * t4[o, (n-1)%56, m, i]
// t4[o, n', m, i] = sum_{j,k} xpad[o, j, n', m+k] * W1[j,k,i]  (pad 3 each side, width)
//
// 112 CTAs (one per (o, out-row n), single wave), 512 threads.
// Stage 2: (m-pair, i) item split across 2 adjacent lanes by j-half; combine via shfl_xor.
// t4 stored [i][m] stride 60; stage 3 reads float4 broadcasts; w0 padded [p][12].

#define NCH 12
#define WID 56
#define XSTRIDE 68          // xs row stride; data cols [4,60); 6*68 % 32 = 24 (no pair-lane conflicts)
#define KS 7
#define NI 9
#define NP 48
#define T4S 60              // t4 row stride (words)
#define W0S 12              // padded w0 row stride
#define THREADS 512

__global__ __launch_bounds__(THREADS, 1)
void fused_sepconv_kernel(const float* __restrict__ x,
                          const float* __restrict__ W0,
                          const float* __restrict__ W1,
                          float* __restrict__ out) {
    __shared__ alignas(16) float xs[NCH * XSTRIDE];   // 816
    __shared__ alignas(16) float w1s[NCH * KS * NI];  // 756
    __shared__ alignas(16) float w0p[NP * W0S];       // 576 (padded; cols 9-11 never read)
    __shared__ alignas(16) float t4s[NI * T4S];       // 540, [i][m]

    const int b = blockIdx.x;             // 0..111
    const int o = b / WID;
    const int n = b % WID;
    const int nin = (n + WID - 1) % WID;  // roll(+1) along height
    const int t = threadIdx.x;

    // ---- Phase 1: global loads issued first (max MLP) ----
    // [0,168): x quads; [168,357): W1 quads; [357,501): W0 3 scalars each
    float4 v = make_float4(0.f, 0.f, 0.f, 0.f);
    float w0v = 0.f, w0v2 = 0.f, w0v3 = 0.f;
    if (t < 168) {
        int j  = t / 14;
        int q4 = t % 14;
        v = *(const float4*)&x[(((o * NCH + j) * WID + nin) * WID) + 4 * q4];
    } else if (t < 357) {
        v = *(const float4*)&W1[4 * (t - 168)];
    } else if (t < 501) {
        w0v  = W0[t - 357];
        w0v2 = W0[t - 357 + 144];
        w0v3 = W0[t - 357 + 288];
    }

    // Zero xs pad columns: cols [0,4) and [60,64) per channel = 24 float4 blocks
    if (t >= 488 && t < 512) {
        int s = t - 488;
        int j = s / 2;
        int side = s % 2;
        *(float4*)&xs[j * XSTRIDE + (side ? 60 : 0)] = make_float4(0.f, 0.f, 0.f, 0.f);
    }

    // Scatter to shared
    if (t < 168) {
        int j  = t / 14;
        int q4 = t % 14;
        *(float4*)&xs[j * XSTRIDE + 4 + 4 * q4] = v;   // 68j+4+4q: 16B aligned
    } else if (t < 357) {
        *(float4*)&w1s[4 * (t - 168)] = v;
    } else if (t < 501) {
        int e0 = t - 357;
        int e1 = e0 + 144;
        int e2 = e0 + 288;
        w0p[(e0 / NI) * W0S + (e0 % NI)] = w0v;
        w0p[(e1 / NI) * W0S + (e1 % NI)] = w0v2;
        w0p[(e2 / NI) * W0S + (e2 % NI)] = w0v3;
    }

    __syncthreads();

    // ---- Stage 2: item = (m-pair, i), split across 2 lanes by j-half ----
    // 504 threads (15.75 warps). group g = t>>1, half = t&1 (j in [6*half, 6*half+6)).
    if (t < 504) {
        const int g    = t >> 1;
        const int half = t & 1;
        const int i    = g % NI;
        const int m0   = 2 * (g / NI);
        const int j0   = 6 * half;

        float accA0 = 0.f, accA1 = 0.f;   // output m0
        float accB0 = 0.f, accB1 = 0.f;   // output m0+1

        #pragma unroll
        for (int jj = 0; jj < 6; ++jj) {
            const int j = j0 + jj;
            float xw[8];
            #pragma unroll
            for (int kk = 0; kk < 8; ++kk)
                xw[kk] = xs[j * XSTRIDE + m0 + 1 + kk];

            #pragma unroll
            for (int k = 0; k < KS; ++k) {
                const float wv = w1s[(j * KS + k) * NI + i];
                if (k & 1) {
                    accA1 = fmaf(xw[k],     wv, accA1);
                    accB1 = fmaf(xw[k + 1], wv, accB1);
                } else {
                    accA0 = fmaf(xw[k],     wv, accA0);
                    accB0 = fmaf(xw[k + 1], wv, accB0);
                }
            }
        }
        float A = accA0 + accA1;
        float B = accB0 + accB1;
        // Warp 15 has only lanes 0..23 active (t<504); pairs (even,odd) all complete.
        const unsigned mask = (t >= 480) ? 0x00FFFFFFu : 0xFFFFFFFFu;
        A += __shfl_xor_sync(mask, A, 1);
        B += __shfl_xor_sync(mask, B, 1);
        if (!half)
            *(float2*)&t4s[i * T4S + m0] = make_float2(A, B);
    }

    __syncthreads();

    // ---- Stage 3: item = (mq, p); 672 items; vector loads + float4 store ----
    for (int item = t; item < 14 * NP; item += THREADS) {
        const int mq = item / NP;         // warp-uniform -> t4 float4 reads broadcast
        const int p  = item % NP;
        const int m0 = 4 * mq;

        float4 wa = *(const float4*)&w0p[p * W0S + 0];
        float4 wb = *(const float4*)&w0p[p * W0S + 4];
        float  w8 = w0p[p * W0S + 8];

        float4 r = make_float4(0.f, 0.f, 0.f, 0.f);
        float* rp = (float*)&r;
        const float wscal[9] = {wa.x, wa.y, wa.z, wa.w, wb.x, wb.y, wb.z, wb.w, w8};

        #pragma unroll
        for (int i = 0; i < NI; ++i) {
            float4 tq = *(const float4*)&t4s[i * T4S + m0];
            rp[0] = fmaf(tq.x, wscal[i], rp[0]);
            rp[1] = fmaf(tq.y, wscal[i], rp[1]);
            rp[2] = fmaf(tq.z, wscal[i], rp[2]);
            rp[3] = fmaf(tq.w, wscal[i], rp[3]);
        }
        *(float4*)&out[(((o * NP + p) * WID + n) * WID) + m0] = r;
    }
}

extern "C" void kernel_launch(void* const* d_in, const int* in_sizes, int n_in,
                              void* d_out, int out_size) {
    // Bind inputs by size: x=75264, W0=432, W1=756
    const float* x  = (const float*)d_in[0];
    const float* W0 = (const float*)d_in[1];
    const float* W1 = (const float*)d_in[2];
    for (int i = 0; i < n_in; ++i) {
        if (in_sizes[i] == 75264) x  = (const float*)d_in[i];
        else if (in_sizes[i] == 432) W0 = (const float*)d_in[i];
        else if (in_sizes[i] == 756) W1 = (const float*)d_in[i];
    }
    float* out = (float*)d_out;

    fused_sepconv_kernel<<<2 * WID, THREADS>>>(x, W0, W1, out);
}

// round 8
// speedup vs baseline: 1.2977x; 1.2977x over previous
#include <cuda_runtime.h>

// y[o*48+p, n, m] = sum_i W0[p,i] * t4[o, (n-1)%56, m, i]
// t4[o, n', m, i] = sum_{j,k} xpad[o, j, n', m+k] * W1[j,k,i]  (pad 3 each side, width)
//
// 224 CTAs: one per (o, out-row n, m-half). 256 threads. 2 CTAs/SM overlap
// each other's barrier stalls; per-CTA critical path ~halved vs the 112-CTA version.

#define NCH 12
#define WID 56
#define MH 28               // m per CTA
#define XOFF 34             // xpad cols needed per channel: MH + 6
#define XS 36               // xs row stride
#define KS 7
#define NI 9
#define NP 48
#define T4S 28              // t4 row stride: [i][m_local]
#define W0S 12              // padded w0 row stride
#define THREADS 256

__global__ __launch_bounds__(THREADS, 2)
void fused_sepconv_kernel(const float* __restrict__ x,
                          const float* __restrict__ W0,
                          const float* __restrict__ W1,
                          float* __restrict__ out) {
    __shared__ float xs[NCH * XS];                    // 432
    __shared__ alignas(16) float w1s[NCH * KS * NI];  // 756
    __shared__ alignas(16) float w0p[NP * W0S];       // 576 (cols 9..11 unused)
    __shared__ alignas(16) float t4s[NI * T4S];       // 252, [i][m_local]

    const int b   = blockIdx.x;           // 0..223
    const int mh  = b & 1;
    const int rem = b >> 1;               // 0..111
    const int o   = rem / WID;
    const int n   = rem % WID;
    const int nin = (n + WID - 1) % WID;  // roll(+1) along height
    const int m0  = MH * mh;              // 0 or 28
    const int t   = threadIdx.x;

    const int xrow = ((o * NCH) * WID + nin) * WID;   // base of channel 0 row

    // ---- Phase 1: loads (x slice predicated-scalar; weights vector/scalar) ----
    // xs[j][off] = xpad[o, j, nin, m0+off] = x col (m0+off-3), zero outside [0,56)
    #pragma unroll
    for (int idx = t; idx < NCH * XOFF; idx += THREADS) {   // 408 -> 2 iters
        int j   = idx / XOFF;
        int off = idx % XOFF;
        int col = m0 + off - 3;
        float val = 0.f;
        if (col >= 0 && col < WID)
            val = x[xrow + j * WID * WID + col];
        xs[j * XS + off] = val;
    }
    // W1: 189 float4
    if (t < 189)
        *(float4*)&w1s[4 * t] = *(const float4*)&W1[4 * t];
    // W0 -> padded rows: 432 scalars, 2 rounds
    {
        int e = t;
        if (e < 432) w0p[(e / NI) * W0S + (e % NI)] = W0[e];
        e = t + THREADS;
        if (e < 432) w0p[(e / NI) * W0S + (e % NI)] = W0[e];
    }

    __syncthreads();

    // ---- Stage 2: thread = (m-pair, i); 126 threads; R5-proven shape ----
    if (t < 14 * NI) {
        const int pair = t / NI;          // 0..13
        const int i    = t % NI;          // lane-fast -> w1 reads consecutive
        const int ml   = 2 * pair;        // local m

        float accA0 = 0.f, accA1 = 0.f;   // output ml
        float accB0 = 0.f, accB1 = 0.f;   // output ml+1

        #pragma unroll
        for (int j = 0; j < NCH; ++j) {
            float xw[8];
            #pragma unroll
            for (int kk = 0; kk < 8; ++kk)
                xw[kk] = xs[j * XS + ml + kk];

            #pragma unroll
            for (int k = 0; k < KS; ++k) {
                const float wv = w1s[(j * KS + k) * NI + i];
                if (k & 1) {
                    accA1 = fmaf(xw[k],     wv, accA1);
                    accB1 = fmaf(xw[k + 1], wv, accB1);
                } else {
                    accA0 = fmaf(xw[k],     wv, accA0);
                    accB0 = fmaf(xw[k + 1], wv, accB0);
                }
            }
        }
        *(float2*)&t4s[i * T4S + ml] = make_float2(accA0 + accA1, accB0 + accB1);
    }

    __syncthreads();

    // ---- Stage 3: item = (p, mq); 336 items; mq lane-fast for coalesced stores ----
    for (int item = t; item < NP * 7; item += THREADS) {
        const int p  = item / 7;
        const int mq = item % 7;          // local m-quad
        const int ml = 4 * mq;

        float4 wa = *(const float4*)&w0p[p * W0S + 0];
        float4 wb = *(const float4*)&w0p[p * W0S + 4];
        float  w8 = w0p[p * W0S + 8];
        const float wscal[9] = {wa.x, wa.y, wa.z, wa.w, wb.x, wb.y, wb.z, wb.w, w8};

        float4 r = make_float4(0.f, 0.f, 0.f, 0.f);
        float* rp = (float*)&r;
        #pragma unroll
        for (int i = 0; i < NI; ++i) {
            float4 tq = *(const float4*)&t4s[i * T4S + ml];
            rp[0] = fmaf(tq.x, wscal[i], rp[0]);
            rp[1] = fmaf(tq.y, wscal[i], rp[1]);
            rp[2] = fmaf(tq.z, wscal[i], rp[2]);
            rp[3] = fmaf(tq.w, wscal[i], rp[3]);
        }
        *(float4*)&out[(((o * NP + p) * WID + n) * WID) + m0 + ml] = r;
    }
}

extern "C" void kernel_launch(void* const* d_in, const int* in_sizes, int n_in,
                              void* d_out, int out_size) {
    // Bind inputs by size: x=75264, W0=432, W1=756
    const float* x  = (const float*)d_in[0];
    const float* W0 = (const float*)d_in[1];
    const float* W1 = (const float*)d_in[2];
    for (int i = 0; i < n_in; ++i) {
        if (in_sizes[i] == 75264) x  = (const float*)d_in[i];
        else if (in_sizes[i] == 432) W0 = (const float*)d_in[i];
        else if (in_sizes[i] == 756) W1 = (const float*)d_in[i];
    }
    float* out = (float*)d_out;

    fused_sepconv_kernel<<<2 * WID * 2, THREADS>>>(x, W0, W1, out);
}